// round 5
// baseline (speedup 1.0000x reference)
#include <cuda_runtime.h>
#include <cuda_bf16.h>
#include <cstdint>

#define BB 8
#define NN 2048
#define DD 128
#define K_TOP 8
#define TILE 128
#define NT 16
#define PAD 132
#define NEG_INF (-3.402823466e38f)

#define STRIDE 68                    // u32 per smem row (bank-conflict-free)
#define LIMB_BYTES (128 * STRIDE * 4)  // 34816

// bf16 limb arrays, packed as u32 = (bf16 k, bf16 k+1); 64 u32 per row
__device__ uint32_t g_lh[BB * NN * 64];
__device__ uint32_t g_lm[BB * NN * 64];
__device__ uint32_t g_ll[BB * NN * 64];

__device__ float g_pval[BB * NN * NT * K_TOP];
__device__ int   g_pidx[BB * NN * NT * K_TOP];

// ---------------------------------------------------------------------------
__device__ __forceinline__ uint32_t smem_u32p(const void* p) {
    uint32_t a;
    asm("{ .reg .u64 t; cvta.to.shared.u64 t, %1; cvt.u32.u64 %0, t; }" : "=r"(a) : "l"(p));
    return a;
}
__device__ __forceinline__ void ldsm4(uint32_t (&r)[4], uint32_t addr) {
    asm volatile("ldmatrix.sync.aligned.m8n8.x4.shared.b16 {%0,%1,%2,%3}, [%4];"
        : "=r"(r[0]), "=r"(r[1]), "=r"(r[2]), "=r"(r[3]) : "r"(addr));
}
__device__ __forceinline__ void mma16(float (&d)[4], const uint32_t* a, const uint32_t* b) {
    asm volatile("mma.sync.aligned.m16n8k16.row.col.f32.bf16.bf16.f32 "
        "{%0,%1,%2,%3}, {%4,%5,%6,%7}, {%8,%9}, {%0,%1,%2,%3};"
        : "+f"(d[0]), "+f"(d[1]), "+f"(d[2]), "+f"(d[3])
        : "r"(a[0]), "r"(a[1]), "r"(a[2]), "r"(a[3]), "r"(b[0]), "r"(b[1]));
}
#define CPA16(d, s)  asm volatile("cp.async.cg.shared.global [%0], [%1], 16;" :: "r"(d), "l"(s))
#define CPA_COMMIT() asm volatile("cp.async.commit_group;" ::: "memory")
#define CPA_WAIT0()  asm volatile("cp.async.wait_group 0;" ::: "memory")

// ---------------------------------------------------------------------------
// 1) normalize + triple bf16 split, packed k-pairs
// ---------------------------------------------------------------------------
__global__ void normsplit_kernel(const float* __restrict__ x) {
    int row  = (blockIdx.x * blockDim.x + threadIdx.x) >> 5;
    int lane = threadIdx.x & 31;
    if (row >= BB * NN) return;
    float4 v = ((const float4*)(x + (size_t)row * DD))[lane];
    float s = v.x * v.x + v.y * v.y + v.z * v.z + v.w * v.w;
    #pragma unroll
    for (int o = 16; o; o >>= 1) s += __shfl_xor_sync(0xffffffffu, s, o);
    float nrm = fmaxf(sqrtf(s), 1e-12f);
    float f[4] = {v.x / nrm, v.y / nrm, v.z / nrm, v.w / nrm};
    uint32_t H[4], M[4], L[4];
    #pragma unroll
    for (int e = 0; e < 4; e++) {
        __nv_bfloat16 hb = __float2bfloat16(f[e]);
        float r1 = f[e] - __bfloat162float(hb);
        __nv_bfloat16 mb = __float2bfloat16(r1);
        float r2 = r1 - __bfloat162float(mb);
        H[e] = __bfloat16_as_ushort(hb);
        M[e] = __bfloat16_as_ushort(mb);
        L[e] = __bfloat16_as_ushort(__float2bfloat16(r2));
    }
    size_t o = (size_t)row * 64 + lane * 2;
    *(uint2*)(g_lh + o) = make_uint2(H[0] | (H[1] << 16), H[2] | (H[3] << 16));
    *(uint2*)(g_lm + o) = make_uint2(M[0] | (M[1] << 16), M[2] | (M[3] << 16));
    *(uint2*)(g_ll + o) = make_uint2(L[0] | (L[1] << 16), L[2] | (L[3] << 16));
}

__global__ void zero_kernel(float4* __restrict__ out, int n4) {
    int i = blockIdx.x * blockDim.x + threadIdx.x;
    int st = gridDim.x * blockDim.x;
    float4 z = make_float4(0.f, 0.f, 0.f, 0.f);
    for (; i < n4; i += st) out[i] = z;
}

// ---------------------------------------------------------------------------
// 2) symmetric tile: bf16 HMMA 6-product GEMM + fused partial top-8
//    grid (136, 8), 512 threads, dyn smem = 6 * 34816 = 208896
// ---------------------------------------------------------------------------
__global__ void __launch_bounds__(512, 1) gemm_topk_kernel() {
    extern __shared__ uint32_t smem_u[];
    float* Cs = (float*)smem_u;            // overlays limb buffers after compute

    int b = blockIdx.y;
    int p = blockIdx.x;
    int I = 0;
    while (p >= NT - I) { p -= NT - I; I++; }
    int J = I + p;

    int tid = threadIdx.x;
    uint32_t sbase = smem_u32p(smem_u);

    // stage 6 limb tiles: m = limb*2 + side (0=A,1=B)
    size_t rowA = (size_t)b * NN + (size_t)I * TILE;
    size_t rowB = (size_t)b * NN + (size_t)J * TILE;
    #pragma unroll
    for (int i = 0; i < 24; i++) {
        int id   = tid + i * 512;
        int m    = id >> 11;           // 0..5
        int w    = id & 2047;
        int row  = w >> 4;
        int part = w & 15;
        int limb = m >> 1, side = m & 1;
        const uint32_t* g = (limb == 0) ? g_lh : (limb == 1) ? g_lm : g_ll;
        const char* src = (const char*)(g + (((side ? rowB : rowA) + row) << 6)) + part * 16;
        uint32_t dst = sbase + (side * 3 + limb) * LIMB_BYTES + row * (STRIDE * 4) + part * 16;
        CPA16(dst, src);
    }
    CPA_COMMIT();
    CPA_WAIT0();
    __syncthreads();

    int lane = tid & 31, w = tid >> 5;
    int lr = lane >> 2, lc = lane & 3;
    int wr = w & 3, wc = w >> 2;
    int mrow = wr * 32, ncol = wc * 32;

    // per-lane ldmatrix address offsets
    uint32_t aoff = (uint32_t)((lane & 15) * (STRIDE * 4) + ((lane & 16) ? 16 : 0));
    uint32_t boff = (uint32_t)((((lane & 16) ? 8 : 0) + (lane & 7)) * (STRIDE * 4) + ((lane & 8) ? 16 : 0));

    float acc[2][4][4];
    #pragma unroll
    for (int mt = 0; mt < 2; mt++)
        #pragma unroll
        for (int nt = 0; nt < 4; nt++)
            #pragma unroll
            for (int q = 0; q < 4; q++) acc[mt][nt][q] = 0.f;

    uint32_t Abase = sbase + mrow * (STRIDE * 4) + aoff;
    uint32_t Bbase = sbase + 3 * LIMB_BYTES + ncol * (STRIDE * 4) + boff;

    #pragma unroll
    for (int ks = 0; ks < 8; ks++) {
        uint32_t af[3][2][4];   // [limb][mt][frag]
        uint32_t bf[3][8];      // [limb][nt*2 + (0=b0? no: pairs)]
        #pragma unroll
        for (int t = 0; t < 3; t++) {
            #pragma unroll
            for (int mt = 0; mt < 2; mt++)
                ldsm4(af[t][mt], Abase + t * LIMB_BYTES + mt * 16 * (STRIDE * 4) + ks * 32);
            #pragma unroll
            for (int g = 0; g < 2; g++)
                ldsm4(*(uint32_t(*)[4])&bf[t][g * 4],
                      Bbase + t * LIMB_BYTES + g * 16 * (STRIDE * 4) + ks * 32);
        }
        // products: hh, hm, mh, mm, hl, lh
        const int pa[6] = {0, 0, 1, 1, 0, 2};
        const int pb[6] = {0, 1, 0, 1, 2, 0};
        #pragma unroll
        for (int pr = 0; pr < 6; pr++) {
            #pragma unroll
            for (int mt = 0; mt < 2; mt++)
                #pragma unroll
                for (int nt = 0; nt < 4; nt++)
                    mma16(acc[mt][nt], af[pa[pr]][mt], &bf[pb[pr]][nt * 2]);
        }
    }

    __syncthreads();   // Cs overlays limb buffers
    #pragma unroll
    for (int mt = 0; mt < 2; mt++)
        #pragma unroll
        for (int nt = 0; nt < 4; nt++) {
            int row = mrow + mt * 16 + lr;
            int col = ncol + nt * 8 + 2 * lc;
            *(float2*)&Cs[row * PAD + col]       = make_float2(acc[mt][nt][0], acc[mt][nt][1]);
            *(float2*)&Cs[(row + 8) * PAD + col] = make_float2(acc[mt][nt][2], acc[mt][nt][3]);
        }
    __syncthreads();

    // --- row pass: top-8 per I-row over J-columns -> slot J ---
    for (int rr = w; rr < TILE; rr += 16) {
        float v[4];
        #pragma unroll
        for (int q = 0; q < 4; q++) v[q] = Cs[rr * PAD + lane + 32 * q];
        size_t grow = (size_t)b * NN + (size_t)I * TILE + rr;
        float* pv = g_pval + (grow * NT + J) * K_TOP;
        int*   pi = g_pidx + (grow * NT + J) * K_TOP;
        #pragma unroll
        for (int t = 0; t < K_TOP; t++) {
            float bv = v[0]; int bc = lane;
            #pragma unroll
            for (int q = 1; q < 4; q++) {
                int c = lane + 32 * q;
                if (v[q] > bv || (v[q] == bv && c < bc)) { bv = v[q]; bc = c; }
            }
            #pragma unroll
            for (int off = 16; off; off >>= 1) {
                float ov = __shfl_xor_sync(0xffffffffu, bv, off);
                int   oc = __shfl_xor_sync(0xffffffffu, bc, off);
                if (ov > bv || (ov == bv && oc < bc)) { bv = ov; bc = oc; }
            }
            if (lane == 0) { pv[t] = bv; pi[t] = J * TILE + bc; }
            if ((bc & 31) == lane) v[bc >> 5] = NEG_INF;
        }
    }

    // --- col pass (off-diagonal only) ---
    if (I != J) {
        for (int cc = w; cc < TILE; cc += 16) {
            float v[4];
            #pragma unroll
            for (int q = 0; q < 4; q++) v[q] = Cs[(lane + 32 * q) * PAD + cc];
            size_t grow = (size_t)b * NN + (size_t)J * TILE + cc;
            float* pv = g_pval + (grow * NT + I) * K_TOP;
            int*   pi = g_pidx + (grow * NT + I) * K_TOP;
            #pragma unroll
            for (int t = 0; t < K_TOP; t++) {
                float bv = v[0]; int br = lane;
                #pragma unroll
                for (int q = 1; q < 4; q++) {
                    int r = lane + 32 * q;
                    if (v[q] > bv || (v[q] == bv && r < br)) { bv = v[q]; br = r; }
                }
                #pragma unroll
                for (int off = 16; off; off >>= 1) {
                    float ov = __shfl_xor_sync(0xffffffffu, bv, off);
                    int   orr = __shfl_xor_sync(0xffffffffu, br, off);
                    if (ov > bv || (ov == bv && orr < br)) { bv = ov; br = orr; }
                }
                if (lane == 0) { pv[t] = bv; pi[t] = I * TILE + br; }
                if ((br & 31) == lane) v[br >> 5] = NEG_INF;
            }
        }
    }
}

// ---------------------------------------------------------------------------
__global__ void merge_scatter_kernel(float* __restrict__ out) {
    int gw   = (blockIdx.x * blockDim.x + threadIdx.x) >> 5;
    int lane = threadIdx.x & 31;
    if (gw >= BB * NN) return;
    int b = gw / NN, n = gw % NN;
    const float* pv = g_pval + (size_t)gw * NT * K_TOP;
    const int*   pi = g_pidx + (size_t)gw * NT * K_TOP;
    float v[4]; int id[4];
    #pragma unroll
    for (int q = 0; q < 4; q++) {
        v[q]  = pv[lane + 32 * q];
        id[q] = pi[lane + 32 * q];
    }
    float* base = out + (size_t)b * NN * NN;
    #pragma unroll
    for (int t = 0; t < K_TOP; t++) {
        float bv = v[0]; int bi = id[0];
        #pragma unroll
        for (int q = 1; q < 4; q++)
            if (v[q] > bv || (v[q] == bv && id[q] < bi)) { bv = v[q]; bi = id[q]; }
        #pragma unroll
        for (int off = 16; off; off >>= 1) {
            float ov = __shfl_xor_sync(0xffffffffu, bv, off);
            int   oi = __shfl_xor_sync(0xffffffffu, bi, off);
            if (ov > bv || (ov == bv && oi < bi)) { bv = ov; bi = oi; }
        }
        if (lane == t) {
            base[(size_t)n * NN + bi] = 1.0f;
            base[(size_t)bi * NN + n] = 1.0f;
        }
        #pragma unroll
        for (int q = 0; q < 4; q++)
            if (id[q] == bi) v[q] = NEG_INF;
    }
    if (lane == 8) base[(size_t)n * NN + n] = 1.0f;
}

// ---------------------------------------------------------------------------
extern "C" void kernel_launch(void* const* d_in, const int* in_sizes, int n_in,
                              void* d_out, int out_size) {
    const float* x = (const float*)d_in[0];
    float* out = (float*)d_out;

    int smem = 6 * LIMB_BYTES;   // 208896
    cudaFuncSetAttribute(gemm_topk_kernel,
                         cudaFuncAttributeMaxDynamicSharedMemorySize, smem);

    normsplit_kernel<<<(BB * NN) / 8, 256>>>(x);
    zero_kernel<<<8192, 256>>>((float4*)out, out_size / 4);
    gemm_topk_kernel<<<dim3(NT * (NT + 1) / 2, BB), 512, smem>>>();
    merge_scatter_kernel<<<(BB * NN) / 8, 256>>>(out);
}